// round 15
// baseline (speedup 1.0000x reference)
#include <cuda_runtime.h>
#include <cuda_fp16.h>
#include <math.h>
#include <stdint.h>

// ---------------- problem constants ----------------
#define NN      65536
#define EE      1048576
#define BB      256
#define LIN_INX 16384
#define LIN_OUTX 6400
#define EPSBN   1e-5f

// ---------------- scratch (device globals; allocation-free) ----------------
__device__ __align__(16) __half g_Ph[NN * 128];   // messages (fp16); head reuses as A16/Y1h
__device__ __align__(16) float g_pre[NN * 128];   // layer-1 accum buffer
__device__ __align__(16) float g_agg[NN * 128];   // layer-2 accum buffer
__device__ __align__(16) float g_bufA[NN * 128];  // layer-3 accum buffer (64-wide)
__device__ __align__(16) float g_mu [BB * LIN_OUTX];  // split-K partial 0 / mu
__device__ __align__(16) float g_sg [BB * LIN_OUTX];  // split-K partial 1 / sigma
__device__ float g_inv[NN];
__device__ int   g_cnt[NN];
__device__ float g_stats[256];
__device__ float g_scale[128];
__device__ float g_shift[128];

__device__ __forceinline__ uint32_t smem_to_u32(const void* p) {
    uint32_t a;
    asm("{ .reg .u64 t; cvta.to.shared.u64 t, %1; cvt.u32.u64 %0, t; }" : "=r"(a) : "l"(p));
    return a;
}
__device__ __forceinline__ void cp_async16(uint32_t sm, const void* g) {
    asm volatile("cp.async.cg.shared.global [%0], [%1], 16;" :: "r"(sm), "l"(g) : "memory");
}
#define CP_COMMIT() asm volatile("cp.async.commit_group;" ::: "memory")
#define CP_WAIT0()  asm volatile("cp.async.wait_group 0;" ::: "memory")
#define CP_WAIT1()  asm volatile("cp.async.wait_group 1;" ::: "memory")

__device__ __forceinline__ uint32_t pack_h2(float x, float y) {
    __half2 h = __float22half2_rn(make_float2(x, y));
    return *(uint32_t*)&h;
}

// ---------------- graph / small kernels ----------------
__global__ void count_edges(const int* __restrict__ dst) {
    int e = blockIdx.x * blockDim.x + threadIdx.x;
    if (e < EE) atomicAdd(&g_cnt[__ldg(dst + e)], 1);
}
__global__ void calc_inv() {
    int i = blockIdx.x * blockDim.x + threadIdx.x;
    if (i < NN) g_inv[i] = 1.0f / fmaxf((float)g_cnt[i], 1.0f);
}
// scatter: acc[dst] += toFloat(Ph[src]) * inv[dst]; fp32 vector reductions into acc.
template<int H>
__global__ void scatter_add_h(const int* __restrict__ src, const int* __restrict__ dst,
                              const __half* __restrict__ P, float* __restrict__ acc) {
    const int H8 = H / 8;
    unsigned idx = blockIdx.x * blockDim.x + threadIdx.x;
    int e = idx / H8;
    int s = idx - e * H8;
    int sn = __ldg(src + e);
    int dn = __ldg(dst + e);
    float inv = __ldg(&g_inv[dn]);
    uint4 r = *(const uint4*)(P + (size_t)sn * H + s * 8);
    float2 f0 = __half22float2(*(__half2*)&r.x);
    float2 f1 = __half22float2(*(__half2*)&r.y);
    float2 f2 = __half22float2(*(__half2*)&r.z);
    float2 f3 = __half22float2(*(__half2*)&r.w);
    float* a = acc + (size_t)dn * H + s * 8;
    asm volatile("red.global.add.v4.f32 [%0], {%1,%2,%3,%4};"
                 :: "l"(a), "f"(f0.x * inv), "f"(f0.y * inv), "f"(f1.x * inv), "f"(f1.y * inv) : "memory");
    asm volatile("red.global.add.v4.f32 [%0], {%1,%2,%3,%4};"
                 :: "l"(a + 4), "f"(f2.x * inv), "f"(f2.y * inv), "f"(f3.x * inv), "f"(f3.y * inv) : "memory");
}
// read-only per-column sum/sumsq over [NN, H]
template<int H>
__global__ void __launch_bounds__(256) stats_only(const float* __restrict__ pre) {
    const int G = 256 / H;
    const int ROWS = 128;
    int tid = threadIdx.x;
    int col = tid % H;
    int rg  = tid / H;
    size_t base = (size_t)blockIdx.x * ROWS;
    float s = 0.f, s2 = 0.f;
    for (int r = rg; r < ROWS; r += G) {
        float v = pre[(base + r) * H + col];
        s += v; s2 += v * v;
    }
    __shared__ float sh[256], sh2[256];
    sh[tid] = s; sh2[tid] = s2;
    __syncthreads();
    if (rg == 0) {
#pragma unroll
        for (int g = 1; g < G; g++) { s += sh[g * H + col]; s2 += sh2[g * H + col]; }
        atomicAdd(&g_stats[col], s);
        atomicAdd(&g_stats[128 + col], s2);
    }
}
template<int H>
__global__ void finalize_stats(const float* __restrict__ gamma, const float* __restrict__ beta) {
    int c = threadIdx.x;
    if (c < H) {
        float m   = g_stats[c] * (1.0f / NN);
        float var = g_stats[128 + c] * (1.0f / NN) - m * m;
        float sc  = gamma[c] * rsqrtf(var + EPSBN);
        g_scale[c] = sc;
        g_shift[c] = beta[c] - m * sc;
    }
}
// layer-3 output: BN+ReLU, fp16 (head GEMM A operand)
__global__ void bn_relu64_h(const float* __restrict__ pre, __half* __restrict__ out) {
    unsigned idx = blockIdx.x * blockDim.x + threadIdx.x;
    float4 v = *(const float4*)(pre + (size_t)idx * 4);
    int c = (idx * 4) & 63;
    v.x = fmaxf(fmaf(v.x, g_scale[c + 0], g_shift[c + 0]), 0.f);
    v.y = fmaxf(fmaf(v.y, g_scale[c + 1], g_shift[c + 1]), 0.f);
    v.z = fmaxf(fmaf(v.z, g_scale[c + 2], g_shift[c + 2]), 0.f);
    v.w = fmaxf(fmaf(v.w, g_scale[c + 3], g_shift[c + 3]), 0.f);
    uint2 o;
    o.x = pack_h2(v.x, v.y);
    o.y = pack_h2(v.z, v.w);
    *(uint2*)(out + (size_t)idx * 4) = o;
}
__global__ void head_bn(const float* __restrict__ P, const float* __restrict__ gamma,
                        const float* __restrict__ beta, float* __restrict__ out) {
    int c = blockIdx.x * blockDim.x + threadIdx.x;
    if (c >= LIN_OUTX) return;
    float s = 0.f, s2 = 0.f;
    for (int r = 0; r < BB; r++) {
        float v = P[(size_t)r * LIN_OUTX + c];
        s += v; s2 += v * v;
    }
    float m   = s * (1.0f / BB);
    float var = s2 * (1.0f / BB) - m * m;
    float sc  = gamma[c] * rsqrtf(var + EPSBN);
    float shf = beta[c] - m * sc;
    for (int r = 0; r < BB; r++)
        out[(size_t)r * LIN_OUTX + c] = P[(size_t)r * LIN_OUTX + c] * sc + shf;
}
__global__ void combine_tanh_h(const float* __restrict__ p0, const float* __restrict__ p1,
                               const float* __restrict__ bias, __half* __restrict__ Y) {
    unsigned i = blockIdx.x * blockDim.x + threadIdx.x;
    float4 a = *(const float4*)(p0 + (size_t)i * 4);
    float4 b = *(const float4*)(p1 + (size_t)i * 4);
    int col = (i * 4) % LIN_OUTX;
    float4 bs = *(const float4*)(bias + col);
    uint2 o;
    o.x = pack_h2(tanhf(a.x + b.x + bs.x), tanhf(a.y + b.y + bs.y));
    o.y = pack_h2(tanhf(a.z + b.z + bs.z), tanhf(a.w + b.w + bs.w));
    *(uint2*)(Y + (size_t)i * 4) = o;
}

// ---------------- fp32 SGEMM (layer GEMMs, K=128) ----------------
template<int HALFOUT, int APPLYBN, int REDOUT>
__global__ void __launch_bounds__(256) sgemm_nt(
    const float* __restrict__ A, const float* __restrict__ W,
    const float* __restrict__ bias, void* __restrict__ Cv,
    int M, int N, int K)
{
    __shared__ float As[16][132];
    __shared__ float Ws[16][68];
    const int tid = threadIdx.x;
    const int m0 = blockIdx.y * 128;
    const int n0 = blockIdx.x * 64;
    const int tx = tid & 15;
    const int ty = tid >> 4;
    const int lr = tid >> 2;
    const int lq = (tid & 3) * 4;

    const float* Ag0 = A + (size_t)(m0 + lr) * K + lq;
    const float* Ag1 = A + (size_t)(m0 + 64 + lr) * K + lq;
    const float* Wg  = W + (size_t)(n0 + lr) * K + lq;

    float acc[8][4];
#pragma unroll
    for (int i = 0; i < 8; i++)
#pragma unroll
        for (int j = 0; j < 4; j++) acc[i][j] = 0.f;

    float4 a0 = *(const float4*)(Ag0);
    float4 a1 = *(const float4*)(Ag1);
    float4 w0 = *(const float4*)(Wg);

    for (int kt = 0; kt < K; kt += 16) {
        if (APPLYBN) {
            float4 sc = *(const float4*)&g_scale[kt + lq];
            float4 sf = *(const float4*)&g_shift[kt + lq];
            a0.x = fmaxf(fmaf(a0.x, sc.x, sf.x), 0.f); a0.y = fmaxf(fmaf(a0.y, sc.y, sf.y), 0.f);
            a0.z = fmaxf(fmaf(a0.z, sc.z, sf.z), 0.f); a0.w = fmaxf(fmaf(a0.w, sc.w, sf.w), 0.f);
            a1.x = fmaxf(fmaf(a1.x, sc.x, sf.x), 0.f); a1.y = fmaxf(fmaf(a1.y, sc.y, sf.y), 0.f);
            a1.z = fmaxf(fmaf(a1.z, sc.z, sf.z), 0.f); a1.w = fmaxf(fmaf(a1.w, sc.w, sf.w), 0.f);
        }
        __syncthreads();
        As[lq + 0][lr]      = a0.x; As[lq + 1][lr]      = a0.y;
        As[lq + 2][lr]      = a0.z; As[lq + 3][lr]      = a0.w;
        As[lq + 0][lr + 64] = a1.x; As[lq + 1][lr + 64] = a1.y;
        As[lq + 2][lr + 64] = a1.z; As[lq + 3][lr + 64] = a1.w;
        Ws[lq + 0][lr] = w0.x; Ws[lq + 1][lr] = w0.y;
        Ws[lq + 2][lr] = w0.z; Ws[lq + 3][lr] = w0.w;
        __syncthreads();

        int kn = kt + 16;
        if (kn < K) {
            a0 = *(const float4*)(Ag0 + kn);
            a1 = *(const float4*)(Ag1 + kn);
            w0 = *(const float4*)(Wg  + kn);
        }
#pragma unroll
        for (int k = 0; k < 16; k++) {
            float4 aa0 = *(const float4*)&As[k][ty * 8];
            float4 aa1 = *(const float4*)&As[k][ty * 8 + 4];
            float4 bb  = *(const float4*)&Ws[k][tx * 4];
            float a[8] = {aa0.x, aa0.y, aa0.z, aa0.w, aa1.x, aa1.y, aa1.z, aa1.w};
            float b[4] = {bb.x, bb.y, bb.z, bb.w};
#pragma unroll
            for (int i = 0; i < 8; i++)
#pragma unroll
                for (int j = 0; j < 4; j++)
                    acc[i][j] = fmaf(a[i], b[j], acc[i][j]);
        }
    }

    float4 bv = make_float4(0.f, 0.f, 0.f, 0.f);
    if (bias) bv = *(const float4*)(bias + n0 + tx * 4);
#pragma unroll
    for (int i = 0; i < 8; i++) {
        float o0 = acc[i][0] + bv.x, o1 = acc[i][1] + bv.y;
        float o2 = acc[i][2] + bv.z, o3 = acc[i][3] + bv.w;
        if (HALFOUT) {
            __half* Ch = (__half*)Cv;
            uint2 o;
            o.x = pack_h2(o0, o1);
            o.y = pack_h2(o2, o3);
            *(uint2*)(Ch + (size_t)(m0 + ty * 8 + i) * N + n0 + tx * 4) = o;
        } else if (REDOUT) {
            float* C = (float*)Cv;
            float* dstp = C + (size_t)(m0 + ty * 8 + i) * N + n0 + tx * 4;
            asm volatile("red.global.add.v4.f32 [%0], {%1,%2,%3,%4};"
                         :: "l"(dstp), "f"(o0), "f"(o1), "f"(o2), "f"(o3) : "memory");
        } else {
            float* C = (float*)Cv;
            *(float4*)(C + (size_t)(m0 + ty * 8 + i) * N + n0 + tx * 4) =
                make_float4(o0, o1, o2, o3);
        }
    }
}

// ---------------- fp16 tensor-core GEMM (head): BM=128, 128 threads, 4 warps ----------------
// 3-stage cp.async pipeline for A (prefetch distance 2),
// W: LDG prefetch distance 2 (two reg sets) + 2-stage smem.
__device__ __forceinline__ void mma_f16(float c[4], const uint32_t a[4], const uint32_t b[2]) {
    asm("mma.sync.aligned.m16n8k16.row.col.f32.f16.f16.f32 "
        "{%0,%1,%2,%3},{%4,%5,%6,%7},{%8,%9},{%0,%1,%2,%3};"
        : "+f"(c[0]), "+f"(c[1]), "+f"(c[2]), "+f"(c[3])
        : "r"(a[0]), "r"(a[1]), "r"(a[2]), "r"(a[3]), "r"(b[0]), "r"(b[1]));
}

#define TPITCH 20
#define ABUF   (128 * TPITCH)          // one A stage (words)
#define WOFF   (3 * ABUF)              // W region start (words)
#define WBUF   (64 * TPITCH)           // one W stage (words)
#define HGEMM_SMEM_BYTES ((3 * ABUF + 2 * WBUF) * 4)   // 40960

__device__ __forceinline__ void gemm_f16ca_core(
    const __half* __restrict__ A16, int lda,
    const float* __restrict__ W, int ldw,
    const float* __restrict__ bias, float* __restrict__ C,
    int N, int Kloop, int n0, int act, uint32_t* sh)
{
    const int tid  = threadIdx.x;
    const int lane = tid & 31;
    const int wid  = tid >> 5;
    const int mw   = wid & 1;
    const int nw   = wid >> 1;
    const int gid  = lane >> 2;
    const int tig  = lane & 3;

    const uint32_t smb = smem_to_u32(sh);

    const __half* Ag = A16 + (size_t)tid * lda;
    const uint32_t a_sm0 = smb + (uint32_t)(tid * TPITCH) * 4;

    const int wrow = tid >> 1;
    const int wq2  = tid & 1;
    const float* Wg = W + (size_t)(n0 + wrow) * ldw + wq2 * 16;
    uint32_t* const wsts = sh + WOFF + wrow * TPITCH + wq2 * 8;

    const int lq   = lane & 15;
    const int lhi4 = (lane >> 4) * 4;
    uint32_t a_lm[4];
#pragma unroll
    for (int i = 0; i < 4; i++)
        a_lm[i] = (uint32_t)(((mw * 64 + i * 16 + lq) * TPITCH + lhi4) * 4);
    const int brow = (lane & 7) + ((lane >> 4) << 3);
    const int bwrd = ((lane >> 3) & 1) * 4;
    uint32_t b_lm[2];
#pragma unroll
    for (int jj = 0; jj < 2; jj++)
        b_lm[jj] = (uint32_t)(((nw * 32 + jj * 16 + brow) * TPITCH + bwrd) * 4);

    float acc[4][4][4];
#pragma unroll
    for (int i = 0; i < 4; i++)
#pragma unroll
        for (int j = 0; j < 4; j++)
#pragma unroll
            for (int q = 0; q < 4; q++) acc[i][j][q] = 0.f;

    float4 wv[2][4];                    // W register double-buffer (distance 2)
    const int ntiles = Kloop / 32;

    // prologue: A(0), A(1) in flight; W(0) -> smem buf0; W(1) -> wv[1]
#pragma unroll
    for (int c = 0; c < 4; c++) cp_async16(a_sm0 + c * 16, Ag + c * 8);
    CP_COMMIT();
    if (ntiles > 1) {
#pragma unroll
        for (int c = 0; c < 4; c++)
            cp_async16(a_sm0 + (uint32_t)ABUF * 4 + c * 16, Ag + 32 + c * 8);
        CP_COMMIT();
    }
#pragma unroll
    for (int q = 0; q < 4; q++) wv[0][q] = *(const float4*)(Wg + q * 4);
#pragma unroll
    for (int q = 0; q < 4; q++) {
        wsts[q * 2]     = pack_h2(wv[0][q].x, wv[0][q].y);
        wsts[q * 2 + 1] = pack_h2(wv[0][q].z, wv[0][q].w);
    }
    if (ntiles > 1) {
#pragma unroll
        for (int q = 0; q < 4; q++) wv[1][q] = *(const float4*)(Wg + 32 + q * 4);
    }
    if (ntiles > 1) CP_WAIT1(); else CP_WAIT0();   // A(0) ready
    __syncthreads();

    for (int it = 0; it < ntiles; it++) {
        const int abuf = it % 3;
        const int wb   = it & 1;
        if (it + 2 < ntiles) {     // issue A(it+2); LDG W(it+2) into freed reg slot
            const int kn = (it + 2) * 32;
            uint32_t adst = a_sm0 + (uint32_t)(((it + 2) % 3) * ABUF) * 4;
#pragma unroll
            for (int c = 0; c < 4; c++) cp_async16(adst + c * 16, Ag + kn + c * 8);
            CP_COMMIT();
            float4* wdst = wv[it & 1];
#pragma unroll
            for (int q = 0; q < 4; q++) wdst[q] = *(const float4*)(Wg + kn + q * 4);
        }

        const uint32_t a_tile = smb + (uint32_t)(abuf * ABUF) * 4;
        const uint32_t w_tile = smb + (uint32_t)(WOFF + wb * WBUF) * 4;

#pragma unroll
        for (int s = 0; s < 2; s++) {
            const uint32_t k0b = (uint32_t)(s * 8 * 4);
            uint32_t afr[4][4], bfr[4][2];
#pragma unroll
            for (int i = 0; i < 4; i++) {
                uint32_t addr = a_tile + a_lm[i] + k0b;
                asm volatile("ldmatrix.sync.aligned.m8n8.x4.shared.b16 {%0,%1,%2,%3}, [%4];"
                             : "=r"(afr[i][0]), "=r"(afr[i][1]), "=r"(afr[i][2]), "=r"(afr[i][3])
                             : "r"(addr));
            }
#pragma unroll
            for (int jj = 0; jj < 2; jj++) {
                uint32_t addr = w_tile + b_lm[jj] + k0b;
                asm volatile("ldmatrix.sync.aligned.m8n8.x4.shared.b16 {%0,%1,%2,%3}, [%4];"
                             : "=r"(bfr[2*jj][0]), "=r"(bfr[2*jj][1]),
                               "=r"(bfr[2*jj+1][0]), "=r"(bfr[2*jj+1][1])
                             : "r"(addr));
            }
#pragma unroll
            for (int i = 0; i < 4; i++)
#pragma unroll
                for (int j = 0; j < 4; j++)
                    mma_f16(acc[i][j], afr[i], bfr[j]);
        }

        if (it + 1 < ntiles) {     // stash W(it+1) from wv[(it+1)&1] into other W buffer
            const float4* wsrc = wv[(it + 1) & 1];
            uint32_t* d = wsts + (wb ^ 1) * WBUF;
#pragma unroll
            for (int q = 0; q < 4; q++) {
                d[q * 2]     = pack_h2(wsrc[q].x, wsrc[q].y);
                d[q * 2 + 1] = pack_h2(wsrc[q].z, wsrc[q].w);
            }
            if (it + 2 < ntiles) CP_WAIT1();   // A(it+1) ready, A(it+2) in flight
            else                 CP_WAIT0();
        }
        __syncthreads();
    }

    // epilogue
#pragma unroll
    for (int i = 0; i < 4; i++) {
        int mrow = mw * 64 + i * 16 + gid;
#pragma unroll
        for (int j = 0; j < 4; j++) {
            int ncol = n0 + nw * 32 + j * 8 + 2 * tig;
            float bx = bias ? bias[ncol] : 0.f;
            float by = bias ? bias[ncol + 1] : 0.f;
            float o0 = acc[i][j][0] + bx, o1 = acc[i][j][1] + by;
            float o2 = acc[i][j][2] + bx, o3 = acc[i][j][3] + by;
            if (act == 2) { o0 = tanhf(o0); o1 = tanhf(o1); o2 = tanhf(o2); o3 = tanhf(o3); }
            *(float2*)(C + (size_t)mrow * N + ncol)       = make_float2(o0, o1);
            *(float2*)(C + (size_t)(mrow + 8) * N + ncol) = make_float2(o2, o3);
        }
    }
}

__global__ void __launch_bounds__(128, 4) gemm_f16ca_wlin(
    const __half* __restrict__ A16, const float* __restrict__ W,
    float* __restrict__ P0, float* __restrict__ P1)
{
    extern __shared__ uint32_t sh[];
    const int nblk = LIN_OUTX / 64;
    const int bx = blockIdx.x;
    const size_t aoff = (size_t)blockIdx.y * 128 * LIN_INX;
    const size_t coff = (size_t)blockIdx.y * 128 * LIN_OUTX;
    if (bx < nblk)
        gemm_f16ca_core(A16 + aoff, LIN_INX, W, LIN_INX, nullptr, P0 + coff,
                        LIN_OUTX, LIN_INX / 2, bx * 64, 0, sh);
    else
        gemm_f16ca_core(A16 + aoff + LIN_INX / 2, LIN_INX, W + LIN_INX / 2, LIN_INX,
                        nullptr, P1 + coff,
                        LIN_OUTX, LIN_INX / 2, (bx - nblk) * 64, 0, sh);
}

__global__ void __launch_bounds__(128, 4) gemm_f16ca_dual(
    const __half* __restrict__ A16,
    const float* __restrict__ W0, const float* __restrict__ b0, float* __restrict__ C0,
    const float* __restrict__ W1, const float* __restrict__ b1, float* __restrict__ C1,
    int N, int K)
{
    extern __shared__ uint32_t sh[];
    int nblk = N / 64;
    int bx = blockIdx.x;
    const size_t aoff = (size_t)blockIdx.y * 128 * K;
    const size_t coff = (size_t)blockIdx.y * 128 * N;
    if (bx < nblk)
        gemm_f16ca_core(A16 + aoff, K, W0, K, b0, C0 + coff, N, K, bx * 64, 0, sh);
    else
        gemm_f16ca_core(A16 + aoff, K, W1, K, b1, C1 + coff, N, K, (bx - nblk) * 64, 0, sh);
}

// ---------------- host orchestration ----------------
static void* symaddr(const void* sym) {
    void* p = nullptr;
    cudaGetSymbolAddress(&p, sym);
    return p;
}

extern "C" void kernel_launch(void* const* d_in, const int* in_sizes, int n_in,
                              void* d_out, int out_size)
{
    const float* x    = (const float*)d_in[0];
    const int*   ei   = (const int*)  d_in[1];
    const int*   srcI = ei;
    const int*   dstI = ei + EE;
    const float *W1l = (const float*)d_in[3],  *b1l = (const float*)d_in[4],  *W1r = (const float*)d_in[5];
    const float *gm1 = (const float*)d_in[6],  *be1 = (const float*)d_in[7];
    const float *W2l = (const float*)d_in[8],  *b2l = (const float*)d_in[9],  *W2r = (const float*)d_in[10];
    const float *gm2 = (const float*)d_in[11], *be2 = (const float*)d_in[12];
    const float *W3l = (const float*)d_in[13], *b3l = (const float*)d_in[14], *W3r = (const float*)d_in[15];
    const float *gm3 = (const float*)d_in[16], *be3 = (const float*)d_in[17];
    const float *Wlin = (const float*)d_in[18], *blin = (const float*)d_in[19];
    const float *Wmu  = (const float*)d_in[20], *bmu  = (const float*)d_in[21];
    const float *Wsig = (const float*)d_in[22], *bsig = (const float*)d_in[23];
    const float *gfx  = (const float*)d_in[24], *bfx  = (const float*)d_in[25];
    const float *gfs  = (const float*)d_in[26], *bfs  = (const float*)d_in[27];
    float* out = (float*)d_out;

    __half* pPh  = (__half*)symaddr(g_Ph);
    float* pPre  = (float*)symaddr(g_pre);    // layer-1 accum
    float* pAgg  = (float*)symaddr(g_agg);    // layer-2 accum
    float* pA    = (float*)symaddr(g_bufA);   // layer-3 accum (64-wide)
    float* pMu   = (float*)symaddr(g_mu);
    float* pSg   = (float*)symaddr(g_sg);
    int*   pCnt  = (int*)  symaddr(g_cnt);
    float* pStat = (float*)symaddr(g_stats);

    __half* pA16  = pPh;                       // [256, 16384] fp16 (layer-3 out)
    __half* pY1h  = pPh + (size_t)NN * 64;     // [256, 6400]  fp16

    static cudaStream_t s2 = nullptr;
    static cudaEvent_t evF = nullptr, evJ = nullptr, evM = nullptr;
    if (!s2) {
        cudaStreamCreateWithFlags(&s2, cudaStreamNonBlocking);
        cudaEventCreateWithFlags(&evF, cudaEventDisableTiming);
        cudaEventCreateWithFlags(&evJ, cudaEventDisableTiming);
        cudaEventCreateWithFlags(&evM, cudaEventDisableTiming);
        cudaFuncSetAttribute(gemm_f16ca_wlin, cudaFuncAttributeMaxDynamicSharedMemorySize, HGEMM_SMEM_BYTES);
        cudaFuncSetAttribute(gemm_f16ca_dual, cudaFuncAttributeMaxDynamicSharedMemorySize, HGEMM_SMEM_BYTES);
    }

    #define FORK() do { cudaEventRecord(evF, 0); cudaStreamWaitEvent(s2, evF, 0); } while (0)
    #define JOIN() do { cudaEventRecord(evJ, s2); cudaStreamWaitEvent(0, evJ, 0); } while (0)
    #define MARK_RDY() cudaEventRecord(evM, s2)
    #define WAIT_RDY() cudaStreamWaitEvent(0, evM, 0)

    const dim3 glF(2, NN / 128);   // layer GEMM, N=128
    const dim3 gl3(1, NN / 128);   // layer-3 GEMM, N=64

    // ---- layer 1: acc = x@W1r^T+b (RED) + scatter(P*inv) (RED) into g_pre ----
    {
        FORK();
        cudaMemsetAsync(pPre, 0, (size_t)NN * 128 * sizeof(float), s2);
        cudaMemsetAsync(pCnt, 0, NN * sizeof(int), s2);
        count_edges<<<EE / 256, 256, 0, s2>>>(dstI);
        calc_inv<<<NN / 256, 256, 0, s2>>>();
        MARK_RDY();                                   // memset + inv ready
        sgemm_nt<0, 0, 1><<<glF, 256, 0, s2>>>(x, W1r, b1l, pPre, NN, 128, 128);
        cudaMemsetAsync(pStat, 0, 256 * sizeof(float), s2);
        sgemm_nt<1, 0, 0><<<glF, 256>>>(x, W1l, nullptr, pPh, NN, 128, 128);
        WAIT_RDY();
        scatter_add_h<128><<<EE * 16 / 256, 256>>>(srcI, dstI, pPh, pPre);
        JOIN();
        stats_only<128><<<NN / 128, 256>>>(pPre);
        finalize_stats<128><<<1, 128>>>(gm1, be1);
    }
    // ---- layer 2: A = BN1(g_pre) fused; acc into g_agg ----
    {
        FORK();
        cudaMemsetAsync(pAgg, 0, (size_t)NN * 128 * sizeof(float), s2);
        MARK_RDY();
        sgemm_nt<0, 1, 1><<<glF, 256, 0, s2>>>(pPre, W2r, b2l, pAgg, NN, 128, 128);
        cudaMemsetAsync(pStat, 0, 256 * sizeof(float), s2);
        sgemm_nt<1, 1, 0><<<glF, 256>>>(pPre, W2l, nullptr, pPh, NN, 128, 128);
        WAIT_RDY();
        scatter_add_h<128><<<EE * 16 / 256, 256>>>(srcI, dstI, pPh, pAgg);
        JOIN();
        stats_only<128><<<NN / 128, 256>>>(pAgg);
        finalize_stats<128><<<1, 128>>>(gm2, be2);
    }
    // ---- layer 3 (H=64): A = BN2(g_agg) fused; acc into g_bufA ----
    {
        FORK();
        cudaMemsetAsync(pA, 0, (size_t)NN * 64 * sizeof(float), s2);
        MARK_RDY();
        sgemm_nt<0, 1, 1><<<gl3, 256, 0, s2>>>(pAgg, W3r, b3l, pA, NN, 64, 128);
        cudaMemsetAsync(pStat, 0, 256 * sizeof(float), s2);
        sgemm_nt<1, 1, 0><<<gl3, 256>>>(pAgg, W3l, nullptr, pPh, NN, 64, 128);
        WAIT_RDY();
        scatter_add_h<64><<<EE * 8 / 256, 256>>>(srcI, dstI, pPh, pA);
        JOIN();
        stats_only<64><<<NN / 128, 256>>>(pA);
        finalize_stats<64><<<1, 64>>>(gm3, be3);
        bn_relu64_h<<<NN * 64 / 4 / 256, 256>>>(pA, pA16);
    }

    // ---- head ----
    {
        gemm_f16ca_wlin<<<dim3(2 * LIN_OUTX / 64, 2), 128, HGEMM_SMEM_BYTES>>>(
            pA16, Wlin, pMu, pSg);
        combine_tanh_h<<<BB * LIN_OUTX / 4 / 256, 256>>>(pMu, pSg, blin, pY1h);
        gemm_f16ca_dual<<<dim3(2 * LIN_OUTX / 64, 2), 128, HGEMM_SMEM_BYTES>>>(
            pY1h, Wmu, bmu, pMu, Wsig, bsig, pSg, LIN_OUTX, LIN_OUTX);
        FORK();
        head_bn<<<(LIN_OUTX + 255) / 256, 256, 0, s2>>>(pSg, gfs, bfs, out + (size_t)BB * LIN_OUTX);
        head_bn<<<(LIN_OUTX + 255) / 256, 256>>>(pMu, gfx, bfx, out);
        JOIN();
    }
    #undef FORK
    #undef JOIN
    #undef MARK_RDY
    #undef WAIT_RDY
}

// round 16
// speedup vs baseline: 1.2421x; 1.2421x over previous
#include <cuda_runtime.h>
#include <cuda_fp16.h>
#include <math.h>
#include <stdint.h>

// ---------------- problem constants ----------------
#define NN      65536
#define EE      1048576
#define BB      256
#define LIN_INX 16384
#define LIN_OUTX 6400
#define EPSBN   1e-5f

// ---------------- scratch (device globals; allocation-free) ----------------
__device__ __align__(16) __half g_Ph[NN * 128];   // messages (fp16); head reuses as A16/Y1h
__device__ __align__(16) float g_pre[NN * 128];   // layer-1 accum buffer
__device__ __align__(16) float g_agg[NN * 128];   // layer-2 accum buffer
__device__ __align__(16) float g_bufA[NN * 128];  // layer-3 accum buffer (64-wide)
__device__ __align__(16) float g_mu [BB * LIN_OUTX];  // split-K partial 0 / mu
__device__ __align__(16) float g_sg [BB * LIN_OUTX];  // split-K partial 1 / sigma
__device__ float g_inv[NN];
__device__ int   g_cnt[NN];
__device__ float g_stats[256];
__device__ float g_scale[128];
__device__ float g_shift[128];

__device__ __forceinline__ uint32_t smem_to_u32(const void* p) {
    uint32_t a;
    asm("{ .reg .u64 t; cvta.to.shared.u64 t, %1; cvt.u32.u64 %0, t; }" : "=r"(a) : "l"(p));
    return a;
}
__device__ __forceinline__ void cp_async16(uint32_t sm, const void* g) {
    asm volatile("cp.async.cg.shared.global [%0], [%1], 16;" :: "r"(sm), "l"(g) : "memory");
}
#define CP_COMMIT() asm volatile("cp.async.commit_group;" ::: "memory")
#define CP_WAIT0()  asm volatile("cp.async.wait_group 0;" ::: "memory")
#define CP_WAIT1()  asm volatile("cp.async.wait_group 1;" ::: "memory")

__device__ __forceinline__ uint32_t pack_h2(float x, float y) {
    __half2 h = __float22half2_rn(make_float2(x, y));
    return *(uint32_t*)&h;
}

// ---------------- graph / small kernels ----------------
__global__ void count_edges(const int* __restrict__ dst) {
    int e = blockIdx.x * blockDim.x + threadIdx.x;
    if (e < EE) atomicAdd(&g_cnt[__ldg(dst + e)], 1);
}
__global__ void calc_inv() {
    int i = blockIdx.x * blockDim.x + threadIdx.x;
    if (i < NN) g_inv[i] = 1.0f / fmaxf((float)g_cnt[i], 1.0f);
}
// scatter: acc[dst] += toFloat(Ph[src]) * inv[dst]; fp32 vector reductions into acc.
template<int H>
__global__ void scatter_add_h(const int* __restrict__ src, const int* __restrict__ dst,
                              const __half* __restrict__ P, float* __restrict__ acc) {
    const int H8 = H / 8;
    unsigned idx = blockIdx.x * blockDim.x + threadIdx.x;
    int e = idx / H8;
    int s = idx - e * H8;
    int sn = __ldg(src + e);
    int dn = __ldg(dst + e);
    float inv = __ldg(&g_inv[dn]);
    uint4 r = *(const uint4*)(P + (size_t)sn * H + s * 8);
    float2 f0 = __half22float2(*(__half2*)&r.x);
    float2 f1 = __half22float2(*(__half2*)&r.y);
    float2 f2 = __half22float2(*(__half2*)&r.z);
    float2 f3 = __half22float2(*(__half2*)&r.w);
    float* a = acc + (size_t)dn * H + s * 8;
    asm volatile("red.global.add.v4.f32 [%0], {%1,%2,%3,%4};"
                 :: "l"(a), "f"(f0.x * inv), "f"(f0.y * inv), "f"(f1.x * inv), "f"(f1.y * inv) : "memory");
    asm volatile("red.global.add.v4.f32 [%0], {%1,%2,%3,%4};"
                 :: "l"(a + 4), "f"(f2.x * inv), "f"(f2.y * inv), "f"(f3.x * inv), "f"(f3.y * inv) : "memory");
}
// read-only per-column sum/sumsq over [NN, H]
template<int H>
__global__ void __launch_bounds__(256) stats_only(const float* __restrict__ pre) {
    const int G = 256 / H;
    const int ROWS = 128;
    int tid = threadIdx.x;
    int col = tid % H;
    int rg  = tid / H;
    size_t base = (size_t)blockIdx.x * ROWS;
    float s = 0.f, s2 = 0.f;
    for (int r = rg; r < ROWS; r += G) {
        float v = pre[(base + r) * H + col];
        s += v; s2 += v * v;
    }
    __shared__ float sh[256], sh2[256];
    sh[tid] = s; sh2[tid] = s2;
    __syncthreads();
    if (rg == 0) {
#pragma unroll
        for (int g = 1; g < G; g++) { s += sh[g * H + col]; s2 += sh2[g * H + col]; }
        atomicAdd(&g_stats[col], s);
        atomicAdd(&g_stats[128 + col], s2);
    }
}
template<int H>
__global__ void finalize_stats(const float* __restrict__ gamma, const float* __restrict__ beta) {
    int c = threadIdx.x;
    if (c < H) {
        float m   = g_stats[c] * (1.0f / NN);
        float var = g_stats[128 + c] * (1.0f / NN) - m * m;
        float sc  = gamma[c] * rsqrtf(var + EPSBN);
        g_scale[c] = sc;
        g_shift[c] = beta[c] - m * sc;
    }
}
// layer-3 output: BN+ReLU, fp16 (head GEMM A operand)
__global__ void bn_relu64_h(const float* __restrict__ pre, __half* __restrict__ out) {
    unsigned idx = blockIdx.x * blockDim.x + threadIdx.x;
    float4 v = *(const float4*)(pre + (size_t)idx * 4);
    int c = (idx * 4) & 63;
    v.x = fmaxf(fmaf(v.x, g_scale[c + 0], g_shift[c + 0]), 0.f);
    v.y = fmaxf(fmaf(v.y, g_scale[c + 1], g_shift[c + 1]), 0.f);
    v.z = fmaxf(fmaf(v.z, g_scale[c + 2], g_shift[c + 2]), 0.f);
    v.w = fmaxf(fmaf(v.w, g_scale[c + 3], g_shift[c + 3]), 0.f);
    uint2 o;
    o.x = pack_h2(v.x, v.y);
    o.y = pack_h2(v.z, v.w);
    *(uint2*)(out + (size_t)idx * 4) = o;
}
__global__ void head_bn(const float* __restrict__ P, const float* __restrict__ gamma,
                        const float* __restrict__ beta, float* __restrict__ out) {
    int c = blockIdx.x * blockDim.x + threadIdx.x;
    if (c >= LIN_OUTX) return;
    float s = 0.f, s2 = 0.f;
    for (int r = 0; r < BB; r++) {
        float v = P[(size_t)r * LIN_OUTX + c];
        s += v; s2 += v * v;
    }
    float m   = s * (1.0f / BB);
    float var = s2 * (1.0f / BB) - m * m;
    float sc  = gamma[c] * rsqrtf(var + EPSBN);
    float shf = beta[c] - m * sc;
    for (int r = 0; r < BB; r++)
        out[(size_t)r * LIN_OUTX + c] = P[(size_t)r * LIN_OUTX + c] * sc + shf;
}
__global__ void combine_tanh_h(const float* __restrict__ p0, const float* __restrict__ p1,
                               const float* __restrict__ bias, __half* __restrict__ Y) {
    unsigned i = blockIdx.x * blockDim.x + threadIdx.x;
    float4 a = *(const float4*)(p0 + (size_t)i * 4);
    float4 b = *(const float4*)(p1 + (size_t)i * 4);
    int col = (i * 4) % LIN_OUTX;
    float4 bs = *(const float4*)(bias + col);
    uint2 o;
    o.x = pack_h2(tanhf(a.x + b.x + bs.x), tanhf(a.y + b.y + bs.y));
    o.y = pack_h2(tanhf(a.z + b.z + bs.z), tanhf(a.w + b.w + bs.w));
    *(uint2*)(Y + (size_t)i * 4) = o;
}

// ---------------- fp32 SGEMM (layer GEMMs, K=128) ----------------
template<int HALFOUT, int APPLYBN, int REDOUT>
__global__ void __launch_bounds__(256) sgemm_nt(
    const float* __restrict__ A, const float* __restrict__ W,
    const float* __restrict__ bias, void* __restrict__ Cv,
    int M, int N, int K)
{
    __shared__ float As[16][132];
    __shared__ float Ws[16][68];
    const int tid = threadIdx.x;
    const int m0 = blockIdx.y * 128;
    const int n0 = blockIdx.x * 64;
    const int tx = tid & 15;
    const int ty = tid >> 4;
    const int lr = tid >> 2;
    const int lq = (tid & 3) * 4;

    const float* Ag0 = A + (size_t)(m0 + lr) * K + lq;
    const float* Ag1 = A + (size_t)(m0 + 64 + lr) * K + lq;
    const float* Wg  = W + (size_t)(n0 + lr) * K + lq;

    float acc[8][4];
#pragma unroll
    for (int i = 0; i < 8; i++)
#pragma unroll
        for (int j = 0; j < 4; j++) acc[i][j] = 0.f;

    float4 a0 = *(const float4*)(Ag0);
    float4 a1 = *(const float4*)(Ag1);
    float4 w0 = *(const float4*)(Wg);

    for (int kt = 0; kt < K; kt += 16) {
        if (APPLYBN) {
            float4 sc = *(const float4*)&g_scale[kt + lq];
            float4 sf = *(const float4*)&g_shift[kt + lq];
            a0.x = fmaxf(fmaf(a0.x, sc.x, sf.x), 0.f); a0.y = fmaxf(fmaf(a0.y, sc.y, sf.y), 0.f);
            a0.z = fmaxf(fmaf(a0.z, sc.z, sf.z), 0.f); a0.w = fmaxf(fmaf(a0.w, sc.w, sf.w), 0.f);
            a1.x = fmaxf(fmaf(a1.x, sc.x, sf.x), 0.f); a1.y = fmaxf(fmaf(a1.y, sc.y, sf.y), 0.f);
            a1.z = fmaxf(fmaf(a1.z, sc.z, sf.z), 0.f); a1.w = fmaxf(fmaf(a1.w, sc.w, sf.w), 0.f);
        }
        __syncthreads();
        As[lq + 0][lr]      = a0.x; As[lq + 1][lr]      = a0.y;
        As[lq + 2][lr]      = a0.z; As[lq + 3][lr]      = a0.w;
        As[lq + 0][lr + 64] = a1.x; As[lq + 1][lr + 64] = a1.y;
        As[lq + 2][lr + 64] = a1.z; As[lq + 3][lr + 64] = a1.w;
        Ws[lq + 0][lr] = w0.x; Ws[lq + 1][lr] = w0.y;
        Ws[lq + 2][lr] = w0.z; Ws[lq + 3][lr] = w0.w;
        __syncthreads();

        int kn = kt + 16;
        if (kn < K) {
            a0 = *(const float4*)(Ag0 + kn);
            a1 = *(const float4*)(Ag1 + kn);
            w0 = *(const float4*)(Wg  + kn);
        }
#pragma unroll
        for (int k = 0; k < 16; k++) {
            float4 aa0 = *(const float4*)&As[k][ty * 8];
            float4 aa1 = *(const float4*)&As[k][ty * 8 + 4];
            float4 bb  = *(const float4*)&Ws[k][tx * 4];
            float a[8] = {aa0.x, aa0.y, aa0.z, aa0.w, aa1.x, aa1.y, aa1.z, aa1.w};
            float b[4] = {bb.x, bb.y, bb.z, bb.w};
#pragma unroll
            for (int i = 0; i < 8; i++)
#pragma unroll
                for (int j = 0; j < 4; j++)
                    acc[i][j] = fmaf(a[i], b[j], acc[i][j]);
        }
    }

    float4 bv = make_float4(0.f, 0.f, 0.f, 0.f);
    if (bias) bv = *(const float4*)(bias + n0 + tx * 4);
#pragma unroll
    for (int i = 0; i < 8; i++) {
        float o0 = acc[i][0] + bv.x, o1 = acc[i][1] + bv.y;
        float o2 = acc[i][2] + bv.z, o3 = acc[i][3] + bv.w;
        if (HALFOUT) {
            __half* Ch = (__half*)Cv;
            uint2 o;
            o.x = pack_h2(o0, o1);
            o.y = pack_h2(o2, o3);
            *(uint2*)(Ch + (size_t)(m0 + ty * 8 + i) * N + n0 + tx * 4) = o;
        } else if (REDOUT) {
            float* C = (float*)Cv;
            float* dstp = C + (size_t)(m0 + ty * 8 + i) * N + n0 + tx * 4;
            asm volatile("red.global.add.v4.f32 [%0], {%1,%2,%3,%4};"
                         :: "l"(dstp), "f"(o0), "f"(o1), "f"(o2), "f"(o3) : "memory");
        } else {
            float* C = (float*)Cv;
            *(float4*)(C + (size_t)(m0 + ty * 8 + i) * N + n0 + tx * 4) =
                make_float4(o0, o1, o2, o3);
        }
    }
}

// ---------------- fp16 tensor-core GEMM (head): BM=128, 128 threads, 4 warps ----------------
// 3-stage cp.async pipeline for A (prefetch distance 2), 2-stage reg->STS for W
// (single W register set: at (128,4) launch bounds there is no register slack).
__device__ __forceinline__ void mma_f16(float c[4], const uint32_t a[4], const uint32_t b[2]) {
    asm("mma.sync.aligned.m16n8k16.row.col.f32.f16.f16.f32 "
        "{%0,%1,%2,%3},{%4,%5,%6,%7},{%8,%9},{%0,%1,%2,%3};"
        : "+f"(c[0]), "+f"(c[1]), "+f"(c[2]), "+f"(c[3])
        : "r"(a[0]), "r"(a[1]), "r"(a[2]), "r"(a[3]), "r"(b[0]), "r"(b[1]));
}

#define TPITCH 20
#define ABUF   (128 * TPITCH)          // one A stage (words)
#define WOFF   (3 * ABUF)              // W region start (words)
#define WBUF   (64 * TPITCH)           // one W stage (words)
#define HGEMM_SMEM_BYTES ((3 * ABUF + 2 * WBUF) * 4)   // 40960

__device__ __forceinline__ void gemm_f16ca_core(
    const __half* __restrict__ A16, int lda,
    const float* __restrict__ W, int ldw,
    const float* __restrict__ bias, float* __restrict__ C,
    int N, int Kloop, int n0, int act, uint32_t* sh)
{
    const int tid  = threadIdx.x;
    const int lane = tid & 31;
    const int wid  = tid >> 5;
    const int mw   = wid & 1;
    const int nw   = wid >> 1;
    const int gid  = lane >> 2;
    const int tig  = lane & 3;

    const uint32_t smb = smem_to_u32(sh);

    const __half* Ag = A16 + (size_t)tid * lda;
    const uint32_t a_sm0 = smb + (uint32_t)(tid * TPITCH) * 4;

    const int wrow = tid >> 1;
    const int wq2  = tid & 1;
    const float* Wg = W + (size_t)(n0 + wrow) * ldw + wq2 * 16;
    uint32_t* const wsts = sh + WOFF + wrow * TPITCH + wq2 * 8;   // W STS base (buf 0)

    const int lq   = lane & 15;
    const int lhi4 = (lane >> 4) * 4;
    uint32_t a_lm[4];
#pragma unroll
    for (int i = 0; i < 4; i++)
        a_lm[i] = (uint32_t)(((mw * 64 + i * 16 + lq) * TPITCH + lhi4) * 4);
    const int brow = (lane & 7) + ((lane >> 4) << 3);
    const int bwrd = ((lane >> 3) & 1) * 4;
    uint32_t b_lm[2];
#pragma unroll
    for (int jj = 0; jj < 2; jj++)
        b_lm[jj] = (uint32_t)(((nw * 32 + jj * 16 + brow) * TPITCH + bwrd) * 4);

    float acc[4][4][4];
#pragma unroll
    for (int i = 0; i < 4; i++)
#pragma unroll
        for (int j = 0; j < 4; j++)
#pragma unroll
            for (int q = 0; q < 4; q++) acc[i][j][q] = 0.f;

    float4 wv[4];
    const int ntiles = Kloop / 32;

    // prologue: A tiles 0,1 in flight; W tile 0 into wbuf0
#pragma unroll
    for (int c = 0; c < 4; c++) cp_async16(a_sm0 + c * 16, Ag + c * 8);
    CP_COMMIT();
    if (ntiles > 1) {
#pragma unroll
        for (int c = 0; c < 4; c++)
            cp_async16(a_sm0 + (uint32_t)ABUF * 4 + c * 16, Ag + 32 + c * 8);
        CP_COMMIT();
    }
#pragma unroll
    for (int q = 0; q < 4; q++) wv[q] = *(const float4*)(Wg + q * 4);
#pragma unroll
    for (int q = 0; q < 4; q++) {
        wsts[q * 2]     = pack_h2(wv[q].x, wv[q].y);
        wsts[q * 2 + 1] = pack_h2(wv[q].z, wv[q].w);
    }
    if (ntiles > 1) CP_WAIT1(); else CP_WAIT0();   // A(0) ready
    __syncthreads();

    for (int it = 0; it < ntiles; it++) {
        const int abuf = it % 3;
        const int wb   = it & 1;
        if (it + 2 < ntiles) {     // issue A(it+2)
            const int kn = (it + 2) * 32;
            uint32_t adst = a_sm0 + (uint32_t)(((it + 2) % 3) * ABUF) * 4;
#pragma unroll
            for (int c = 0; c < 4; c++) cp_async16(adst + c * 16, Ag + kn + c * 8);
            CP_COMMIT();
        }
        if (it + 1 < ntiles) {     // load W(it+1) into regs
            const int kn = (it + 1) * 32;
#pragma unroll
            for (int q = 0; q < 4; q++) wv[q] = *(const float4*)(Wg + kn + q * 4);
        }

        const uint32_t a_tile = smb + (uint32_t)(abuf * ABUF) * 4;
        const uint32_t w_tile = smb + (uint32_t)(WOFF + wb * WBUF) * 4;

#pragma unroll
        for (int s = 0; s < 2; s++) {
            const uint32_t k0b = (uint32_t)(s * 8 * 4);
            uint32_t afr[4][4], bfr[4][2];
#pragma unroll
            for (int i = 0; i < 4; i++) {
                uint32_t addr = a_tile + a_lm[i] + k0b;
                asm volatile("ldmatrix.sync.aligned.m8n8.x4.shared.b16 {%0,%1,%2,%3}, [%4];"
                             : "=r"(afr[i][0]), "=r"(afr[i][1]), "=r"(afr[i][2]), "=r"(afr[i][3])
                             : "r"(addr));
            }
#pragma unroll
            for (int jj = 0; jj < 2; jj++) {
                uint32_t addr = w_tile + b_lm[jj] + k0b;
                asm volatile("ldmatrix.sync.aligned.m8n8.x4.shared.b16 {%0,%1,%2,%3}, [%4];"
                             : "=r"(bfr[2*jj][0]), "=r"(bfr[2*jj][1]),
                               "=r"(bfr[2*jj+1][0]), "=r"(bfr[2*jj+1][1])
                             : "r"(addr));
            }
#pragma unroll
            for (int i = 0; i < 4; i++)
#pragma unroll
                for (int j = 0; j < 4; j++)
                    mma_f16(acc[i][j], afr[i], bfr[j]);
        }

        if (it + 1 < ntiles) {     // stash W(it+1) fp16 into the other W buffer
            uint32_t* d = wsts + (wb ^ 1) * WBUF;
#pragma unroll
            for (int q = 0; q < 4; q++) {
                d[q * 2]     = pack_h2(wv[q].x, wv[q].y);
                d[q * 2 + 1] = pack_h2(wv[q].z, wv[q].w);
            }
            if (it + 2 < ntiles) CP_WAIT1();   // A(it+1) ready, A(it+2) in flight
            else                 CP_WAIT0();   // drain tail
        }
        __syncthreads();
    }

    // epilogue
#pragma unroll
    for (int i = 0; i < 4; i++) {
        int mrow = mw * 64 + i * 16 + gid;
#pragma unroll
        for (int j = 0; j < 4; j++) {
            int ncol = n0 + nw * 32 + j * 8 + 2 * tig;
            float bx = bias ? bias[ncol] : 0.f;
            float by = bias ? bias[ncol + 1] : 0.f;
            float o0 = acc[i][j][0] + bx, o1 = acc[i][j][1] + by;
            float o2 = acc[i][j][2] + bx, o3 = acc[i][j][3] + by;
            if (act == 2) { o0 = tanhf(o0); o1 = tanhf(o1); o2 = tanhf(o2); o3 = tanhf(o3); }
            *(float2*)(C + (size_t)mrow * N + ncol)       = make_float2(o0, o1);
            *(float2*)(C + (size_t)(mrow + 8) * N + ncol) = make_float2(o2, o3);
        }
    }
}

__global__ void __launch_bounds__(128, 4) gemm_f16ca_wlin(
    const __half* __restrict__ A16, const float* __restrict__ W,
    float* __restrict__ P0, float* __restrict__ P1)
{
    extern __shared__ uint32_t sh[];
    const int nblk = LIN_OUTX / 64;
    const int bx = blockIdx.x;
    const size_t aoff = (size_t)blockIdx.y * 128 * LIN_INX;
    const size_t coff = (size_t)blockIdx.y * 128 * LIN_OUTX;
    if (bx < nblk)
        gemm_f16ca_core(A16 + aoff, LIN_INX, W, LIN_INX, nullptr, P0 + coff,
                        LIN_OUTX, LIN_INX / 2, bx * 64, 0, sh);
    else
        gemm_f16ca_core(A16 + aoff + LIN_INX / 2, LIN_INX, W + LIN_INX / 2, LIN_INX,
                        nullptr, P1 + coff,
                        LIN_OUTX, LIN_INX / 2, (bx - nblk) * 64, 0, sh);
}

__global__ void __launch_bounds__(128, 4) gemm_f16ca_dual(
    const __half* __restrict__ A16,
    const float* __restrict__ W0, const float* __restrict__ b0, float* __restrict__ C0,
    const float* __restrict__ W1, const float* __restrict__ b1, float* __restrict__ C1,
    int N, int K)
{
    extern __shared__ uint32_t sh[];
    int nblk = N / 64;
    int bx = blockIdx.x;
    const size_t aoff = (size_t)blockIdx.y * 128 * K;
    const size_t coff = (size_t)blockIdx.y * 128 * N;
    if (bx < nblk)
        gemm_f16ca_core(A16 + aoff, K, W0, K, b0, C0 + coff, N, K, bx * 64, 0, sh);
    else
        gemm_f16ca_core(A16 + aoff, K, W1, K, b1, C1 + coff, N, K, (bx - nblk) * 64, 0, sh);
}

// ---------------- host orchestration ----------------
static void* symaddr(const void* sym) {
    void* p = nullptr;
    cudaGetSymbolAddress(&p, sym);
    return p;
}

extern "C" void kernel_launch(void* const* d_in, const int* in_sizes, int n_in,
                              void* d_out, int out_size)
{
    const float* x    = (const float*)d_in[0];
    const int*   ei   = (const int*)  d_in[1];
    const int*   srcI = ei;
    const int*   dstI = ei + EE;
    const float *W1l = (const float*)d_in[3],  *b1l = (const float*)d_in[4],  *W1r = (const float*)d_in[5];
    const float *gm1 = (const float*)d_in[6],  *be1 = (const float*)d_in[7];
    const float *W2l = (const float*)d_in[8],  *b2l = (const float*)d_in[9],  *W2r = (const float*)d_in[10];
    const float *gm2 = (const float*)d_in[11], *be2 = (const float*)d_in[12];
    const float *W3l = (const float*)d_in[13], *b3l = (const float*)d_in[14], *W3r = (const float*)d_in[15];
    const float *gm3 = (const float*)d_in[16], *be3 = (const float*)d_in[17];
    const float *Wlin = (const float*)d_in[18], *blin = (const float*)d_in[19];
    const float *Wmu  = (const float*)d_in[20], *bmu  = (const float*)d_in[21];
    const float *Wsig = (const float*)d_in[22], *bsig = (const float*)d_in[23];
    const float *gfx  = (const float*)d_in[24], *bfx  = (const float*)d_in[25];
    const float *gfs  = (const float*)d_in[26], *bfs  = (const float*)d_in[27];
    float* out = (float*)d_out;

    __half* pPh  = (__half*)symaddr(g_Ph);
    float* pPre  = (float*)symaddr(g_pre);    // layer-1 accum
    float* pAgg  = (float*)symaddr(g_agg);    // layer-2 accum
    float* pA    = (float*)symaddr(g_bufA);   // layer-3 accum (64-wide)
    float* pMu   = (float*)symaddr(g_mu);
    float* pSg   = (float*)symaddr(g_sg);
    int*   pCnt  = (int*)  symaddr(g_cnt);
    float* pStat = (float*)symaddr(g_stats);

    __half* pA16  = pPh;                       // [256, 16384] fp16 (layer-3 out)
    __half* pY1h  = pPh + (size_t)NN * 64;     // [256, 6400]  fp16

    static cudaStream_t s2 = nullptr;
    static cudaEvent_t evF = nullptr, evJ = nullptr, evM = nullptr;
    if (!s2) {
        cudaStreamCreateWithFlags(&s2, cudaStreamNonBlocking);
        cudaEventCreateWithFlags(&evF, cudaEventDisableTiming);
        cudaEventCreateWithFlags(&evJ, cudaEventDisableTiming);
        cudaEventCreateWithFlags(&evM, cudaEventDisableTiming);
        cudaFuncSetAttribute(gemm_f16ca_wlin, cudaFuncAttributeMaxDynamicSharedMemorySize, HGEMM_SMEM_BYTES);
        cudaFuncSetAttribute(gemm_f16ca_dual, cudaFuncAttributeMaxDynamicSharedMemorySize, HGEMM_SMEM_BYTES);
    }

    #define FORK() do { cudaEventRecord(evF, 0); cudaStreamWaitEvent(s2, evF, 0); } while (0)
    #define JOIN() do { cudaEventRecord(evJ, s2); cudaStreamWaitEvent(0, evJ, 0); } while (0)
    #define MARK_RDY() cudaEventRecord(evM, s2)
    #define WAIT_RDY() cudaStreamWaitEvent(0, evM, 0)

    const dim3 glF(2, NN / 128);   // layer GEMM, N=128
    const dim3 gl3(1, NN / 128);   // layer-3 GEMM, N=64

    // ---- layer 1: acc = x@W1r^T+b (RED) + scatter(P*inv) (RED) into g_pre ----
    {
        FORK();
        cudaMemsetAsync(pPre, 0, (size_t)NN * 128 * sizeof(float), s2);
        cudaMemsetAsync(pCnt, 0, NN * sizeof(int), s2);
        count_edges<<<EE / 256, 256, 0, s2>>>(dstI);
        calc_inv<<<NN / 256, 256, 0, s2>>>();
        MARK_RDY();                                   // memset + inv ready
        sgemm_nt<0, 0, 1><<<glF, 256, 0, s2>>>(x, W1r, b1l, pPre, NN, 128, 128);
        cudaMemsetAsync(pStat, 0, 256 * sizeof(float), s2);
        sgemm_nt<1, 0, 0><<<glF, 256>>>(x, W1l, nullptr, pPh, NN, 128, 128);
        WAIT_RDY();
        scatter_add_h<128><<<EE * 16 / 256, 256>>>(srcI, dstI, pPh, pPre);
        JOIN();
        stats_only<128><<<NN / 128, 256>>>(pPre);
        finalize_stats<128><<<1, 128>>>(gm1, be1);
    }
    // ---- layer 2: A = BN1(g_pre) fused; acc into g_agg ----
    {
        FORK();
        cudaMemsetAsync(pAgg, 0, (size_t)NN * 128 * sizeof(float), s2);
        MARK_RDY();
        sgemm_nt<0, 1, 1><<<glF, 256, 0, s2>>>(pPre, W2r, b2l, pAgg, NN, 128, 128);
        cudaMemsetAsync(pStat, 0, 256 * sizeof(float), s2);
        sgemm_nt<1, 1, 0><<<glF, 256>>>(pPre, W2l, nullptr, pPh, NN, 128, 128);
        WAIT_RDY();
        scatter_add_h<128><<<EE * 16 / 256, 256>>>(srcI, dstI, pPh, pAgg);
        JOIN();
        stats_only<128><<<NN / 128, 256>>>(pAgg);
        finalize_stats<128><<<1, 128>>>(gm2, be2);
    }
    // ---- layer 3 (H=64): A = BN2(g_agg) fused; acc into g_bufA ----
    {
        FORK();
        cudaMemsetAsync(pA, 0, (size_t)NN * 64 * sizeof(float), s2);
        MARK_RDY();
        sgemm_nt<0, 1, 1><<<gl3, 256, 0, s2>>>(pAgg, W3r, b3l, pA, NN, 64, 128);
        cudaMemsetAsync(pStat, 0, 256 * sizeof(float), s2);
        sgemm_nt<1, 1, 0><<<gl3, 256>>>(pAgg, W3l, nullptr, pPh, NN, 64, 128);
        WAIT_RDY();
        scatter_add_h<64><<<EE * 8 / 256, 256>>>(srcI, dstI, pPh, pA);
        JOIN();
        stats_only<64><<<NN / 128, 256>>>(pA);
        finalize_stats<64><<<1, 64>>>(gm3, be3);
        bn_relu64_h<<<NN * 64 / 4 / 256, 256>>>(pA, pA16);
    }

    // ---- head ----
    {
        gemm_f16ca_wlin<<<dim3(2 * LIN_OUTX / 64, 2), 128, HGEMM_SMEM_BYTES>>>(
            pA16, Wlin, pMu, pSg);
        combine_tanh_h<<<BB * LIN_OUTX / 4 / 256, 256>>>(pMu, pSg, blin, pY1h);
        gemm_f16ca_dual<<<dim3(2 * LIN_OUTX / 64, 2), 128, HGEMM_SMEM_BYTES>>>(
            pY1h, Wmu, bmu, pMu, Wsig, bsig, pSg, LIN_OUTX, LIN_OUTX);
        FORK();
        head_bn<<<(LIN_OUTX + 255) / 256, 256, 0, s2>>>(pSg, gfs, bfs, out + (size_t)BB * LIN_OUTX);
        head_bn<<<(LIN_OUTX + 255) / 256, 256>>>(pMu, gfx, bfx, out);
        JOIN();
    }
    #undef FORK
    #undef JOIN
    #undef MARK_RDY
    #undef WAIT_RDY
}